// round 12
// baseline (speedup 1.0000x reference)
#include <cuda_runtime.h>

// Cox partial-likelihood loss, n = 8192 — SINGLE fused kernel:
// sort + suffix-scan + search + finalize with an in-kernel release/acquire
// barrier (all 256 blocks are co-resident in one wave, so spinning is safe).
//
// loss = -mean_i[ (theta_i - log(sum_{j: t_j>=t_i} exp(theta_j) + eps)) * e_i ]
// S_i is a suffix sum over t-sorted order.
//
// Grid (16 chunks x 16 i-tiles) x 512 threads:
//   Phase A (blocks with ib==0 only): bitonic-sort chunk c of (t, exp(risk))
//     [shfl stages j<32, smem stages j>=32], warp-shuffle suffix scan,
//     publish sorted-t + suffix(+sentinel), release-increment g_sort_ready.
//   Barrier: every block spins on ld.acquire.gpu until g_sort_ready == 16.
//   Phase B (all blocks): stage chunk c tables to smem, 1 branchless
//     lower_bound per thread (512 i's per tile), write partial.
//   Tile election among the 16 chunk-blocks: elected block sums the 16
//     partials per i in fixed order, applies log/event mask, block-reduces.
//   Global election among the 16 tiles: fixed-order final sum, writes
//     -sum/n, resets ALL counters for the next graph replay.
//
// Fixed comparator network + fixed-order sums -> deterministic.
// No device allocations, no fp atomics, graph-capturable.

#define N        8192
#define CHUNK    512
#define NCHUNK   16
#define BLOCK    512
#define NTILE    16            // N / BLOCK
#define EPS_F    1e-8f

__device__ float g_tsorted[N];
__device__ float g_sfx[NCHUNK * (CHUNK + 1)];
__device__ float g_partS[NCHUNK * N];
__device__ float g_bsum[NTILE];
__device__ int   g_sort_ready;          // zero-init
__device__ int   g_done_it[NTILE];      // zero-init
__device__ int   g_done_final;          // zero-init

__device__ __forceinline__ void bstage_shfl(float& key, float& val,
                                            int j, int k, int tid) {
    const float bk = __shfl_xor_sync(0xffffffffu, key, j);
    const float bv = __shfl_xor_sync(0xffffffffu, val, j);
    const bool lower = (tid & j) == 0;
    const bool up    = (tid & k) == 0;
    const bool take_b = (up == lower) ? (bk < key) : (bk > key);
    if (take_b) { key = bk; val = bv; }
}

__global__ __launch_bounds__(BLOCK, 2) void cox_fused(
    const float* __restrict__ risk,
    const float* __restrict__ t,
    const float* __restrict__ e,
    float* __restrict__ out,
    int n)
{
    __shared__ float sk[CHUNK];         // sort keys / scratch
    __shared__ float sv[CHUNK];         // sort payload / scratch
    __shared__ float ts[CHUNK];         // staged sorted-t for search
    __shared__ float sf[CHUNK + 1];     // staged suffix table
    __shared__ float red[BLOCK];
    __shared__ float wsum[BLOCK / 32];
    __shared__ int   flag;

    const int c   = blockIdx.x;         // chunk   0..15
    const int ib  = blockIdx.y;         // i-tile  0..15
    const int tid = threadIdx.x;
    const int lane = tid & 31;
    const int w    = tid >> 5;

    // ================= Phase A: sort + scan (one block per chunk) =========
    if (ib == 0) {
        const int base = c * CHUNK;
        float key = t[base + tid];
        float val = expf(risk[base + tid]);

#pragma unroll
        for (int k = 2; k <= 32; k <<= 1)
#pragma unroll
            for (int j = k >> 1; j >= 1; j >>= 1)
                bstage_shfl(key, val, j, k, tid);

        for (int k = 64; k <= CHUNK; k <<= 1) {
            for (int j = k >> 1; j >= 32; j >>= 1) {
                sk[tid] = key; sv[tid] = val;
                __syncthreads();
                const int p = tid ^ j;
                const float bk = sk[p], bv = sv[p];
                const bool lower = (tid & j) == 0;
                const bool up    = (tid & k) == 0;
                const bool take_b = (up == lower) ? (bk < key) : (bk > key);
                if (take_b) { key = bk; val = bv; }
                __syncthreads();
            }
#pragma unroll
            for (int j = 16; j >= 1; j >>= 1)
                bstage_shfl(key, val, j, k, tid);
        }

        // inclusive suffix scan: warp shfl + cross-warp fixup
        float v = val;
#pragma unroll
        for (int off = 1; off < 32; off <<= 1) {
            const float x = __shfl_down_sync(0xffffffffu, v, off);
            if (lane + off < 32) v += x;
        }
        if (lane == 0) wsum[w] = v;
        __syncthreads();
        float add = 0.0f;
        for (int ww = w + 1; ww < BLOCK / 32; ww++)   // fixed order
            add += wsum[ww];
        v += add;

        g_tsorted[c * CHUNK + tid] = key;
        g_sfx[c * (CHUNK + 1) + tid] = v;
        if (tid == 0) g_sfx[c * (CHUNK + 1) + CHUNK] = 0.0f;

        __threadfence();                 // release the published tables
        __syncthreads();
        if (tid == 0) atomicAdd(&g_sort_ready, 1);
    }

    // ================= Barrier: wait for all 16 chunks ====================
    if (tid == 0) {
        int v;
        do {
            asm volatile("ld.global.acquire.gpu.b32 %0, [%1];"
                         : "=r"(v) : "l"(&g_sort_ready));
        } while (v < NCHUNK);
    }
    __syncthreads();

    // ================= Phase B: search ====================================
    for (int idx = tid; idx < CHUNK; idx += BLOCK)
        ts[idx] = g_tsorted[c * CHUNK + idx];
    for (int idx = tid; idx < CHUNK + 1; idx += BLOCK)
        sf[idx] = g_sfx[c * (CHUNK + 1) + idx];
    __syncthreads();

    const int   i  = ib * BLOCK + tid;   // one i per thread
    const float ti = t[i];

    int pos = 0;                         // lower_bound: #elems with t < ti
#pragma unroll
    for (int bit = CHUNK >> 1; bit >= 1; bit >>= 1)
        if (ts[pos + bit - 1] < ti) pos += bit;
    if (ts[pos] < ti) pos++;             // allow pos == CHUNK

    g_partS[c * n + i] = sf[pos];

    // ---- tile election among 16 chunk-blocks
    __threadfence();
    __syncthreads();
    if (tid == 0)
        flag = (atomicAdd(&g_done_it[ib], 1) == NCHUNK - 1);
    __syncthreads();
    if (!flag) return;

    __threadfence();                     // acquire all 16 partials

    float S = 0.0f;                      // 16 independent LDGs, fixed order
#pragma unroll
    for (int cc = 0; cc < NCHUNK; cc++)
        S += __ldcg(&g_partS[cc * n + i]);

    float acc = (risk[i] - logf(S + EPS_F)) * e[i];

    // fixed-order block reduction of 512 values
    red[tid] = acc;
    __syncthreads();
    if (tid < 256) red[tid] += red[tid + 256];
    __syncthreads();
    if (tid < 128) red[tid] += red[tid + 128];
    __syncthreads();
    if (tid < 64)  red[tid] += red[tid + 64];
    __syncthreads();
    if (tid < 32) {
        float v = red[tid] + red[tid + 32];
#pragma unroll
        for (int off = 16; off > 0; off >>= 1)
            v += __shfl_down_sync(0xffffffffu, v, off);

        if (tid == 0) {
            g_bsum[ib] = v;
            __threadfence();
            if (atomicAdd(&g_done_final, 1) == NTILE - 1) {
                __threadfence();
                float total = 0.0f;
                for (int b = 0; b < NTILE; b++)   // fixed order
                    total += __ldcg(&g_bsum[b]);
                out[0] = -total / (float)n;

                // reset for next graph replay
                g_sort_ready = 0;
                g_done_final = 0;
                for (int b = 0; b < NTILE; b++) g_done_it[b] = 0;
                __threadfence();
            }
        }
    }
}

// ---------------------------------------------------------------- launch
extern "C" void kernel_launch(void* const* d_in, const int* in_sizes, int n_in,
                              void* d_out, int out_size) {
    const float* risk = (const float*)d_in[0];
    const float* t    = (const float*)d_in[1];
    const float* e    = (const float*)d_in[2];
    float* out = (float*)d_out;

    const int n = in_sizes[0];   // 8192

    cox_fused<<<dim3(NCHUNK, NTILE), BLOCK>>>(risk, t, e, out, n);
}